// round 2
// baseline (speedup 1.0000x reference)
#include <cuda_runtime.h>
#include <math.h>

#define NN 50000
#define NE 800000
#define HD 128

// ---- scratch (device globals; no allocation allowed) ----
__device__ __align__(256) float g_x[NN * HD];
__device__ __align__(256) float g_agg[NN * HD];
__device__ __align__(256) float g_h1[NN * HD];
__device__ __align__(256) float g_h2[NN * HD];
__device__ __align__(256) float g_cnt[NN];

__device__ __forceinline__ void red_add_v4(float* addr, float4 v) {
    asm volatile("red.global.add.v4.f32 [%0], {%1,%2,%3,%4};"
                 :: "l"(addr), "f"(v.x), "f"(v.y), "f"(v.z), "f"(v.w)
                 : "memory");
}

// ---- prep: gather x = emb[node_id], zero agg & cnt ----
__global__ void prep_kernel(const int* __restrict__ node_id,
                            const float* __restrict__ emb) {
    int t = blockIdx.x * blockDim.x + threadIdx.x;
    if (t >= NN * 32) return;
    int row = t >> 5, q = t & 31;
    int nid = node_id[row];
    float4 v = ((const float4*)emb)[(size_t)nid * 32 + q];
    ((float4*)g_x)[(size_t)row * 32 + q] = v;
    ((float4*)g_agg)[t] = make_float4(0.f, 0.f, 0.f, 0.f);
    if (q == 0) g_cnt[row] = 0.f;
}

__global__ void zero_agg_kernel() {
    int t = blockIdx.x * blockDim.x + threadIdx.x;
    if (t < NN * 32) ((float4*)g_agg)[t] = make_float4(0.f, 0.f, 0.f, 0.f);
}

__global__ void count_kernel(const int* __restrict__ dst) {
    int e = blockIdx.x * blockDim.x + threadIdx.x;
    if (e < NE) atomicAdd(&g_cnt[dst[e]], 1.0f);
}

// ---- scatter: warp per edge; lane = one float4 of the 512B feature row ----
__global__ void scatter_kernel(const float* __restrict__ feat,
                               const int* __restrict__ src,
                               const int* __restrict__ dst) {
    int gt = blockIdx.x * blockDim.x + threadIdx.x;
    int e = gt >> 5;
    if (e >= NE) return;
    int lane = gt & 31;
    int s = src[e], d = dst[e];
    float4 v = ((const float4*)feat)[(size_t)s * 32 + lane];
    red_add_v4(&g_agg[(size_t)d * HD + lane * 4], v);
}

// ---- fused SAGE layer: out = (agg/max(cnt,1)) @ Wl^T + bl + xin @ Wr^T ----
// Block: 256 threads, 64 rows x 128 cols of output.
// smem: Wl[128][132] + Wr[128][132] (padded pitch -> conflict-free) + A/X tiles.
#define WPITCH 132
template <bool RELU>
__global__ __launch_bounds__(256)
void layer_kernel(const float* __restrict__ Wl, const float* __restrict__ bl,
                  const float* __restrict__ Wr,
                  const float* __restrict__ xin, float* __restrict__ outp) {
    extern __shared__ float sm[];
    float* sWl = sm;                       // 128*132
    float* sWr = sm + 128 * WPITCH;        // 128*132
    float* sA  = sm + 2 * 128 * WPITCH;    // 64*128
    float* sX  = sA + 64 * HD;             // 64*128

    int tid = threadIdx.x;
    for (int i = tid; i < 128 * 128; i += 256) {
        int r = i >> 7, c = i & 127;
        sWl[r * WPITCH + c] = Wl[i];
        sWr[r * WPITCH + c] = Wr[i];
    }
    int row0 = blockIdx.x * 64;
    for (int i = tid; i < 64 * 32; i += 256) {
        int r = i >> 5, q = i & 31;
        int gr = row0 + r;
        float4 a = make_float4(0.f, 0.f, 0.f, 0.f);
        float4 x = a;
        if (gr < NN) {
            float inv = 1.0f / fmaxf(g_cnt[gr], 1.0f);
            a = ((const float4*)g_agg)[(size_t)gr * 32 + q];
            a.x *= inv; a.y *= inv; a.z *= inv; a.w *= inv;
            x = ((const float4*)xin)[(size_t)gr * 32 + q];
        }
        ((float4*)sA)[i] = a;
        ((float4*)sX)[i] = x;
    }
    __syncthreads();

    int cg = tid & 31;     // output column group (lane)
    int rg = tid >> 5;     // row group (warp id): broadcast A reads in-warp
    float acc[8][4];
#pragma unroll
    for (int i = 0; i < 8; i++)
#pragma unroll
        for (int j = 0; j < 4; j++) acc[i][j] = 0.f;

    const float* Amat = sA;
    const float* Wmat = sWl;
#pragma unroll 1
    for (int m = 0; m < 2; m++) {
#pragma unroll 4
        for (int k = 0; k < HD; k += 4) {
            float4 b[4];
#pragma unroll
            for (int j = 0; j < 4; j++)
                b[j] = *(const float4*)&Wmat[(cg + 32 * j) * WPITCH + k];
#pragma unroll
            for (int i = 0; i < 8; i++) {
                float4 a = *(const float4*)&Amat[(rg * 8 + i) * HD + k];
#pragma unroll
                for (int j = 0; j < 4; j++) {
                    acc[i][j] += a.x * b[j].x;
                    acc[i][j] += a.y * b[j].y;
                    acc[i][j] += a.z * b[j].z;
                    acc[i][j] += a.w * b[j].w;
                }
            }
        }
        Amat = sX;
        Wmat = sWr;
    }

#pragma unroll
    for (int i = 0; i < 8; i++) {
        int gr = row0 + rg * 8 + i;
        if (gr < NN) {
#pragma unroll
            for (int j = 0; j < 4; j++) {
                int c = cg + 32 * j;
                float v = acc[i][j] + bl[c];
                if (RELU) v = fmaxf(v, 0.f);
                outp[(size_t)gr * HD + c] = v;
            }
        }
    }
}

// ---- edge classifier: 8 threads per edge, interleaved float4 loads ----
__global__ void edge_dot_kernel(const int* __restrict__ src,
                                const int* __restrict__ dst,
                                float* __restrict__ outp) {
    int gt = blockIdx.x * blockDim.x + threadIdx.x;
    int e = gt >> 3;
    if (e >= NE) return;
    int sub = gt & 7;
    int s = src[e], d = dst[e];
    const float4* hs = (const float4*)&g_h2[(size_t)s * HD];
    const float4* hd = (const float4*)&g_h2[(size_t)d * HD];
    float acc = 0.f;
#pragma unroll
    for (int t = 0; t < 4; t++) {
        float4 a = hs[sub + t * 8];
        float4 b = hd[sub + t * 8];
        acc += a.x * b.x + a.y * b.y + a.z * b.z + a.w * b.w;
    }
    acc += __shfl_xor_sync(0xffffffffu, acc, 1);
    acc += __shfl_xor_sync(0xffffffffu, acc, 2);
    acc += __shfl_xor_sync(0xffffffffu, acc, 4);
    if (sub == 0) outp[e] = acc;
}

extern "C" void kernel_launch(void* const* d_in, const int* in_sizes, int n_in,
                              void* d_out, int out_size) {
    const int* node_id = (const int*)d_in[0];
    const int* edge_index = (const int*)d_in[1];
    const float* emb = (const float*)d_in[2];
    const float* Wl1 = (const float*)d_in[3];
    const float* bl1 = (const float*)d_in[4];
    const float* Wr1 = (const float*)d_in[5];
    const float* Wl2 = (const float*)d_in[6];
    const float* bl2 = (const float*)d_in[7];
    const float* Wr2 = (const float*)d_in[8];
    const int* src = edge_index;
    const int* dst = edge_index + NE;
    float* outp = (float*)d_out;

    float *px, *ph1, *ph2;
    cudaGetSymbolAddress((void**)&px, g_x);
    cudaGetSymbolAddress((void**)&ph1, g_h1);
    cudaGetSymbolAddress((void**)&ph2, g_h2);

    int smem = (2 * 128 * WPITCH + 2 * 64 * HD) * (int)sizeof(float);
    cudaFuncSetAttribute(layer_kernel<true>,
                         cudaFuncAttributeMaxDynamicSharedMemorySize, smem);
    cudaFuncSetAttribute(layer_kernel<false>,
                         cudaFuncAttributeMaxDynamicSharedMemorySize, smem);

    const int TB = 256;
    int g_prep = (NN * 32 + TB - 1) / TB;
    int g_cnt_ = (NE + TB - 1) / TB;
    int g_scat = (NE * 32 + TB - 1) / TB;   // warp per edge
    int g_lay  = (NN + 63) / 64;
    int g_edge = (NE * 8 + TB - 1) / TB;

    prep_kernel<<<g_prep, TB>>>(node_id, emb);
    count_kernel<<<g_cnt_, TB>>>(dst);
    scatter_kernel<<<g_scat, TB>>>(px, src, dst);
    layer_kernel<true><<<g_lay, TB, smem>>>(Wl1, bl1, Wr1, px, ph1);
    zero_agg_kernel<<<g_prep, TB>>>();
    scatter_kernel<<<g_scat, TB>>>(ph1, src, dst);
    layer_kernel<false><<<g_lay, TB, smem>>>(Wl2, bl2, Wr2, ph1, ph2);
    edge_dot_kernel<<<g_edge, TB>>>(src, dst, outp);
}

// round 4
// speedup vs baseline: 1.1148x; 1.1148x over previous
#include <cuda_runtime.h>
#include <cuda_bf16.h>
#include <cstdint>

#define NN 50000
#define NE 800000
#define HD 128

// ---- scratch (device globals; no allocation allowed) ----
__device__ __align__(256) float g_x[NN * HD];
__device__ __align__(256) float g_agg[NN * HD];
__device__ __align__(256) float g_h1[NN * HD];
__device__ __align__(256) float g_h2[NN * HD];
__device__ __align__(256) float g_cnt[NN];

__device__ __forceinline__ uint32_t smem_to_u32(const void* smem_ptr) {
    uint32_t addr;
    asm("{ .reg .u64 tmp; cvta.to.shared.u64 tmp, %1; cvt.u32.u64 %0, tmp; }"
        : "=r"(addr) : "l"(smem_ptr));
    return addr;
}

__device__ __forceinline__ void red_add_v4(float* addr, float4 v) {
    asm volatile("red.global.add.v4.f32 [%0], {%1,%2,%3,%4};"
                 :: "l"(addr), "f"(v.x), "f"(v.y), "f"(v.z), "f"(v.w)
                 : "memory");
}

// ================= graph-op kernels (passing, unchanged) =================
__global__ void prep_kernel(const int* __restrict__ node_id,
                            const float* __restrict__ emb) {
    int t = blockIdx.x * blockDim.x + threadIdx.x;
    if (t >= NN * 32) return;
    int row = t >> 5, q = t & 31;
    int nid = node_id[row];
    float4 v = ((const float4*)emb)[(size_t)nid * 32 + q];
    ((float4*)g_x)[(size_t)row * 32 + q] = v;
    ((float4*)g_agg)[t] = make_float4(0.f, 0.f, 0.f, 0.f);
    if (q == 0) g_cnt[row] = 0.f;
}

__global__ void zero_agg_kernel() {
    int t = blockIdx.x * blockDim.x + threadIdx.x;
    if (t < NN * 32) ((float4*)g_agg)[t] = make_float4(0.f, 0.f, 0.f, 0.f);
}

__global__ void count_kernel(const int* __restrict__ dst) {
    int e = blockIdx.x * blockDim.x + threadIdx.x;
    if (e < NE) atomicAdd(&g_cnt[dst[e]], 1.0f);
}

__global__ void scatter_kernel(const float* __restrict__ feat,
                               const int* __restrict__ src,
                               const int* __restrict__ dst) {
    int gt = blockIdx.x * blockDim.x + threadIdx.x;
    int e = gt >> 5;
    if (e >= NE) return;
    int lane = gt & 31;
    int s = src[e], d = dst[e];
    float4 v = ((const float4*)feat)[(size_t)s * 32 + lane];
    red_add_v4(&g_agg[(size_t)d * HD + lane * 4], v);
}

__global__ void edge_dot_kernel(const int* __restrict__ src,
                                const int* __restrict__ dst,
                                float* __restrict__ outp) {
    int gt = blockIdx.x * blockDim.x + threadIdx.x;
    int e = gt >> 3;
    if (e >= NE) return;
    int sub = gt & 7;
    int s = src[e], d = dst[e];
    const float4* hs = (const float4*)&g_h2[(size_t)s * HD];
    const float4* hd = (const float4*)&g_h2[(size_t)d * HD];
    float acc = 0.f;
#pragma unroll
    for (int t = 0; t < 4; t++) {
        float4 a = hs[sub + t * 8];
        float4 b = hd[sub + t * 8];
        acc += a.x * b.x + a.y * b.y + a.z * b.z + a.w * b.w;
    }
    acc += __shfl_xor_sync(0xffffffffu, acc, 1);
    acc += __shfl_xor_sync(0xffffffffu, acc, 2);
    acc += __shfl_xor_sync(0xffffffffu, acc, 4);
    if (sub == 0) outp[e] = acc;
}

// ================= mma.sync split-bf16 SAGE layer =================
// out[m, 0:128] = concat(agg/max(cnt,1), x)[m, 0:256] @ Wcat^T + bl  (+relu)
// 3 passes: Ah*Wh + Ah*Wl + Al*Wh, fp32 accumulation (err ~2^-16).
#define TILE_M 64
#define WP 264            // bf16 pitch: 132 words -> row starts at bank 4i, conflict-free
#define SMB_BIAS 0        // 512 B
#define SMB_WHI  512
#define SMB_WLO  (512 + 128 * WP * 2)               // +67584
#define SMB_AHI  (512 + 2 * 128 * WP * 2)           // 135680
#define SMB_ALO  (SMB_AHI + TILE_M * WP * 2)        // +33792
#define SMB_TOT  (SMB_ALO + TILE_M * WP * 2)        // 203264

__device__ __forceinline__ void split2(float a, uint16_t& h, uint16_t& l) {
    __nv_bfloat16 hb = __float2bfloat16(a);
    float r = a - __bfloat162float(hb);
    __nv_bfloat16 lb = __float2bfloat16(r);
    h = __bfloat16_as_ushort(hb);
    l = __bfloat16_as_ushort(lb);
}

__device__ __forceinline__ void ldsm_x4(uint32_t& r0, uint32_t& r1,
                                        uint32_t& r2, uint32_t& r3, uint32_t a) {
    asm volatile("ldmatrix.sync.aligned.m8n8.x4.shared.b16 {%0,%1,%2,%3}, [%4];"
                 : "=r"(r0), "=r"(r1), "=r"(r2), "=r"(r3) : "r"(a));
}

__device__ __forceinline__ void mma16816(float* c, uint32_t a0, uint32_t a1,
                                         uint32_t a2, uint32_t a3,
                                         uint32_t b0, uint32_t b1) {
    asm volatile(
        "mma.sync.aligned.m16n8k16.row.col.f32.bf16.bf16.f32 "
        "{%0,%1,%2,%3}, {%4,%5,%6,%7}, {%8,%9}, {%0,%1,%2,%3};"
        : "+f"(c[0]), "+f"(c[1]), "+f"(c[2]), "+f"(c[3])
        : "r"(a0), "r"(a1), "r"(a2), "r"(a3), "r"(b0), "r"(b1));
}

template <bool RELU>
__global__ __launch_bounds__(256)
void tc_layer_kernel(const float* __restrict__ Wl, const float* __restrict__ bl,
                     const float* __restrict__ Wr,
                     const float* __restrict__ xin, float* __restrict__ outp) {
    extern __shared__ char smem[];
    uint32_t sb = smem_to_u32(smem);
    int tid = threadIdx.x;
    int lane = tid & 31;
    int wid = tid >> 5;

    if (tid < 128) ((float*)(smem + SMB_BIAS))[tid] = bl[tid];

    // ---- load + split W (128 x 256) into hi/lo smem ----
#pragma unroll 4
    for (int idx = tid; idx < 128 * 64; idx += 256) {
        int n = idx >> 6, q = idx & 63, k = q << 2;
        float4 v = (k < 128) ? ((const float4*)Wl)[n * 32 + q]
                             : ((const float4*)Wr)[n * 32 + q - 32];
        uint16_t h0,l0,h1,l1,h2,l2,h3,l3;
        split2(v.x, h0, l0); split2(v.y, h1, l1);
        split2(v.z, h2, l2); split2(v.w, h3, l3);
        uint32_t off = (uint32_t)(n * WP + k) * 2;
        *(uint2*)(smem + SMB_WHI + off) =
            make_uint2(((uint32_t)h1 << 16) | h0, ((uint32_t)h3 << 16) | h2);
        *(uint2*)(smem + SMB_WLO + off) =
            make_uint2(((uint32_t)l1 << 16) | l0, ((uint32_t)l3 << 16) | l2);
    }

    // ---- load + split A tile (64 x 256 = [agg/cnt | x]) ----
    int row0 = blockIdx.x * TILE_M;
#pragma unroll 4
    for (int idx = tid; idx < TILE_M * 64; idx += 256) {
        int r = idx >> 6, q = idx & 63, k = q << 2;
        int gr = row0 + r;
        uint2 hv = make_uint2(0u, 0u), lv = hv;
        if (gr < NN) {
            float4 v; float sc;
            if (k < 128) {
                sc = 1.f / fmaxf(g_cnt[gr], 1.f);
                v = ((const float4*)&g_agg[(size_t)gr * HD])[q];
            } else {
                sc = 1.f;
                v = ((const float4*)&xin[(size_t)gr * HD])[q - 32];
            }
            uint16_t h0,l0,h1,l1,h2,l2,h3,l3;
            split2(v.x * sc, h0, l0); split2(v.y * sc, h1, l1);
            split2(v.z * sc, h2, l2); split2(v.w * sc, h3, l3);
            hv = make_uint2(((uint32_t)h1 << 16) | h0, ((uint32_t)h3 << 16) | h2);
            lv = make_uint2(((uint32_t)l1 << 16) | l0, ((uint32_t)l3 << 16) | l2);
        }
        uint32_t off = (uint32_t)(r * WP + k) * 2;
        *(uint2*)(smem + SMB_AHI + off) = hv;
        *(uint2*)(smem + SMB_ALO + off) = lv;
    }
    __syncthreads();

    // ---- mma: warp w -> rows m0 = (w/2)*16, cols n0 = (w%2)*64 ----
    int m0 = (wid >> 1) * 16;
    int n0 = (wid & 1) * 64;
    float acc[8][4];
#pragma unroll
    for (int j = 0; j < 8; j++)
#pragma unroll
        for (int c = 0; c < 4; c++) acc[j][c] = 0.f;

    // ldmatrix address components (bf16 units -> bytes)
    uint32_t a_row = (uint32_t)(m0 + (lane & 15));
    uint32_t a_koff = (uint32_t)((lane >> 4) << 3);
    // B x4: two n-tiles per load; lanes 0-15 tile jt*2, lanes 16-31 tile jt*2+1
    uint32_t b_row_base = (uint32_t)(n0 + ((lane >> 4) << 3) + (lane & 7));
    uint32_t b_koff = (uint32_t)(((lane >> 3) & 1) << 3);

#pragma unroll 1
    for (int p = 0; p < 3; p++) {
        uint32_t Abase = sb + ((p == 2) ? SMB_ALO : SMB_AHI);
        uint32_t Wbase = sb + ((p == 1) ? SMB_WLO : SMB_WHI);
        uint32_t aaddr = Abase + (a_row * WP + a_koff) * 2;
        uint32_t baddr0 = Wbase + (b_row_base * WP + b_koff) * 2;
#pragma unroll
        for (int s = 0; s < 16; s++) {
            uint32_t k0b = (uint32_t)(s << 4) * 2;  // 16 bf16 = 32 bytes
            uint32_t a0, a1, a2, a3;
            ldsm_x4(a0, a1, a2, a3, aaddr + k0b);
#pragma unroll
            for (int jt = 0; jt < 4; jt++) {
                uint32_t b0, b1, b2, b3;
                ldsm_x4(b0, b1, b2, b3,
                        baddr0 + (uint32_t)(jt * 16 * WP) * 2 + k0b);
                mma16816(acc[jt * 2], a0, a1, a2, a3, b0, b1);
                mma16816(acc[jt * 2 + 1], a0, a1, a2, a3, b2, b3);
            }
        }
    }

    // ---- epilogue: bias (+relu), store fp32 ----
    const float* sbias = (const float*)(smem + SMB_BIAS);
    int gid = lane >> 2, tq = lane & 3;
    int r_lo = row0 + m0 + gid;
    int r_hi = r_lo + 8;
#pragma unroll
    for (int j = 0; j < 8; j++) {
        int col = n0 + j * 8 + tq * 2;
        float b0 = sbias[col], b1 = sbias[col + 1];
        if (r_lo < NN) {
            float v0 = acc[j][0] + b0, v1 = acc[j][1] + b1;
            if (RELU) { v0 = fmaxf(v0, 0.f); v1 = fmaxf(v1, 0.f); }
            *(float2*)&outp[(size_t)r_lo * HD + col] = make_float2(v0, v1);
        }
        if (r_hi < NN) {
            float v2 = acc[j][2] + b0, v3 = acc[j][3] + b1;
            if (RELU) { v2 = fmaxf(v2, 0.f); v3 = fmaxf(v3, 0.f); }
            *(float2*)&outp[(size_t)r_hi * HD + col] = make_float2(v2, v3);
        }
    }
}

// ================= launch =================
extern "C" void kernel_launch(void* const* d_in, const int* in_sizes, int n_in,
                              void* d_out, int out_size) {
    const int* node_id = (const int*)d_in[0];
    const int* edge_index = (const int*)d_in[1];
    const float* emb = (const float*)d_in[2];
    const float* Wl1 = (const float*)d_in[3];
    const float* bl1 = (const float*)d_in[4];
    const float* Wr1 = (const float*)d_in[5];
    const float* Wl2 = (const float*)d_in[6];
    const float* bl2 = (const float*)d_in[7];
    const float* Wr2 = (const float*)d_in[8];
    const int* src = edge_index;
    const int* dst = edge_index + NE;
    float* outp = (float*)d_out;

    float *px, *ph1, *ph2;
    cudaGetSymbolAddress((void**)&px, g_x);
    cudaGetSymbolAddress((void**)&ph1, g_h1);
    cudaGetSymbolAddress((void**)&ph2, g_h2);

    cudaFuncSetAttribute(tc_layer_kernel<true>,
                         cudaFuncAttributeMaxDynamicSharedMemorySize, SMB_TOT);
    cudaFuncSetAttribute(tc_layer_kernel<false>,
                         cudaFuncAttributeMaxDynamicSharedMemorySize, SMB_TOT);

    const int TB = 256;
    int g_prep = (NN * 32 + TB - 1) / TB;
    int g_cnt_ = (NE + TB - 1) / TB;
    int g_scat = (NE * 32 + TB - 1) / TB;
    int g_lay  = (NN + TILE_M - 1) / TILE_M;
    int g_edge = (NE * 8 + TB - 1) / TB;

    prep_kernel<<<g_prep, TB>>>(node_id, emb);
    count_kernel<<<g_cnt_, TB>>>(dst);
    scatter_kernel<<<g_scat, TB>>>(px, src, dst);
    tc_layer_kernel<true><<<g_lay, TB, SMB_TOT>>>(Wl1, bl1, Wr1, px, ph1);
    zero_agg_kernel<<<g_prep, TB>>>();
    scatter_kernel<<<g_scat, TB>>>(ph1, src, dst);
    tc_layer_kernel<false><<<g_lay, TB, SMB_TOT>>>(Wl2, bl2, Wr2, ph1, ph2);
    edge_dot_kernel<<<g_edge, TB>>>(src, dst, outp);
}

// round 5
// speedup vs baseline: 1.1821x; 1.0604x over previous
#include <cuda_runtime.h>
#include <cuda_bf16.h>
#include <cstdint>

#define NN 50000
#define NE 800000
#define HD 128
#define NTILES ((NN + 63) / 64)

// ---- scratch (device globals; no allocation allowed) ----
__device__ __align__(256) float g_x[NN * HD];
__device__ __align__(256) float g_agg[NN * HD];
__device__ __align__(256) float g_h1[NN * HD];
__device__ __align__(256) float g_h2[NN * HD];
__device__ __align__(256) float g_cnt[NN];

__device__ __forceinline__ uint32_t smem_to_u32(const void* smem_ptr) {
    uint32_t addr;
    asm("{ .reg .u64 tmp; cvta.to.shared.u64 tmp, %1; cvt.u32.u64 %0, tmp; }"
        : "=r"(addr) : "l"(smem_ptr));
    return addr;
}

__device__ __forceinline__ void red_add_v4(float* addr, float4 v) {
    asm volatile("red.global.add.v4.f32 [%0], {%1,%2,%3,%4};"
                 :: "l"(addr), "f"(v.x), "f"(v.y), "f"(v.z), "f"(v.w)
                 : "memory");
}

// ================= graph-op kernels =================
__global__ void prep_kernel(const int* __restrict__ node_id,
                            const float* __restrict__ emb) {
    int t = blockIdx.x * blockDim.x + threadIdx.x;
    if (t >= NN * 32) return;
    int row = t >> 5, q = t & 31;
    int nid = node_id[row];
    float4 v = ((const float4*)emb)[(size_t)nid * 32 + q];
    ((float4*)g_x)[(size_t)row * 32 + q] = v;
    ((float4*)g_agg)[t] = make_float4(0.f, 0.f, 0.f, 0.f);
    if (q == 0) g_cnt[row] = 0.f;
}

__global__ void count_kernel(const int* __restrict__ dst) {
    int e = blockIdx.x * blockDim.x + threadIdx.x;
    if (e < NE) atomicAdd(&g_cnt[dst[e]], 1.0f);
}

__global__ void scatter_kernel(const float* __restrict__ feat,
                               const int* __restrict__ src,
                               const int* __restrict__ dst) {
    int gt = blockIdx.x * blockDim.x + threadIdx.x;
    int e = gt >> 5;
    if (e >= NE) return;
    int lane = gt & 31;
    int s = src[e], d = dst[e];
    float4 v = ((const float4*)feat)[(size_t)s * 32 + lane];
    red_add_v4(&g_agg[(size_t)d * HD + lane * 4], v);
}

__global__ void edge_dot_kernel(const int* __restrict__ src,
                                const int* __restrict__ dst,
                                float* __restrict__ outp) {
    int gt = blockIdx.x * blockDim.x + threadIdx.x;
    int e = gt >> 3;
    if (e >= NE) return;
    int sub = gt & 7;
    int s = src[e], d = dst[e];
    const float4* hs = (const float4*)&g_h2[(size_t)s * HD];
    const float4* hd = (const float4*)&g_h2[(size_t)d * HD];
    float acc = 0.f;
#pragma unroll
    for (int t = 0; t < 4; t++) {
        float4 a = hs[sub + t * 8];
        float4 b = hd[sub + t * 8];
        acc += a.x * b.x + a.y * b.y + a.z * b.z + a.w * b.w;
    }
    acc += __shfl_xor_sync(0xffffffffu, acc, 1);
    acc += __shfl_xor_sync(0xffffffffu, acc, 2);
    acc += __shfl_xor_sync(0xffffffffu, acc, 4);
    if (sub == 0) outp[e] = acc;
}

// ================= persistent mma.sync split-bf16 SAGE layer =================
// out[m, 0:128] = concat(agg/max(cnt,1), x)[m, 0:256] @ Wcat^T + bl  (+relu)
// 3 passes: Ah*Wh + Ah*Wl + Al*Wh, fp32 accumulation.
// W split+loaded ONCE per CTA; CTA loops over M-tiles (grid = 148 persistent).
#define TILE_M 64
#define WP 264
#define SMB_BIAS 0
#define SMB_WHI  512
#define SMB_WLO  (512 + 128 * WP * 2)
#define SMB_AHI  (512 + 2 * 128 * WP * 2)
#define SMB_ALO  (SMB_AHI + TILE_M * WP * 2)
#define SMB_TOT  (SMB_ALO + TILE_M * WP * 2)

__device__ __forceinline__ uint32_t pack_bf2(float lo, float hi) {
    uint32_t r;
    asm("cvt.rn.bf16x2.f32 %0, %1, %2;" : "=r"(r) : "f"(hi), "f"(lo));
    return r;
}
// split float4 into hi/lo bf16x2 pairs; bf16->fp32 reconstruct is a shift.
__device__ __forceinline__ void split4(float4 v, uint2& hv, uint2& lv) {
    hv.x = pack_bf2(v.x, v.y);
    hv.y = pack_bf2(v.z, v.w);
    float rx = v.x - __uint_as_float(hv.x << 16);
    float ry = v.y - __uint_as_float(hv.x & 0xffff0000u);
    float rz = v.z - __uint_as_float(hv.y << 16);
    float rw = v.w - __uint_as_float(hv.y & 0xffff0000u);
    lv.x = pack_bf2(rx, ry);
    lv.y = pack_bf2(rz, rw);
}

__device__ __forceinline__ void ldsm_x4(uint32_t& r0, uint32_t& r1,
                                        uint32_t& r2, uint32_t& r3, uint32_t a) {
    asm volatile("ldmatrix.sync.aligned.m8n8.x4.shared.b16 {%0,%1,%2,%3}, [%4];"
                 : "=r"(r0), "=r"(r1), "=r"(r2), "=r"(r3) : "r"(a));
}

__device__ __forceinline__ void mma16816(float* c, uint32_t a0, uint32_t a1,
                                         uint32_t a2, uint32_t a3,
                                         uint32_t b0, uint32_t b1) {
    asm volatile(
        "mma.sync.aligned.m16n8k16.row.col.f32.bf16.bf16.f32 "
        "{%0,%1,%2,%3}, {%4,%5,%6,%7}, {%8,%9}, {%0,%1,%2,%3};"
        : "+f"(c[0]), "+f"(c[1]), "+f"(c[2]), "+f"(c[3])
        : "r"(a0), "r"(a1), "r"(a2), "r"(a3), "r"(b0), "r"(b1));
}

template <bool RELU, bool ZERO_AGG>
__global__ __launch_bounds__(256, 1)
void tc_layer_kernel(const float* __restrict__ Wl, const float* __restrict__ bl,
                     const float* __restrict__ Wr,
                     const float* __restrict__ xin, float* __restrict__ outp) {
    extern __shared__ char smem[];
    uint32_t sb = smem_to_u32(smem);
    int tid = threadIdx.x;
    int lane = tid & 31;
    int wid = tid >> 5;

    if (tid < 128) ((float*)(smem + SMB_BIAS))[tid] = bl[tid];

    // ---- W (128 x 256) split into hi/lo smem: ONCE per CTA ----
#pragma unroll 4
    for (int idx = tid; idx < 128 * 64; idx += 256) {
        int n = idx >> 6, q = idx & 63, k = q << 2;
        float4 v = (k < 128) ? ((const float4*)Wl)[n * 32 + q]
                             : ((const float4*)Wr)[n * 32 + q - 32];
        uint2 hv, lv;
        split4(v, hv, lv);
        uint32_t off = (uint32_t)(n * WP + k) * 2;
        *(uint2*)(smem + SMB_WHI + off) = hv;
        *(uint2*)(smem + SMB_WLO + off) = lv;
    }
    __syncthreads();

    // fragment address components (constant across tiles)
    int m0 = (wid >> 1) * 16;
    int n0 = (wid & 1) * 64;
    uint32_t a_row = (uint32_t)(m0 + (lane & 15));
    uint32_t a_koff = (uint32_t)((lane >> 4) << 3);
    uint32_t b_row_base = (uint32_t)(n0 + ((lane >> 4) << 3) + (lane & 7));
    uint32_t b_koff = (uint32_t)(((lane >> 3) & 1) << 3);
    const float* sbias = (const float*)(smem + SMB_BIAS);
    int gid = lane >> 2, tq = lane & 3;

    for (int t = blockIdx.x; t < NTILES; t += gridDim.x) {
        int row0 = t * TILE_M;

        // ---- A tile (64 x 256 = [agg/cnt | x]) load + split ----
#pragma unroll 2
        for (int idx = tid; idx < TILE_M * 64; idx += 256) {
            int r = idx >> 6, q = idx & 63, k = q << 2;
            int gr = row0 + r;
            uint2 hv = make_uint2(0u, 0u), lv = hv;
            if (gr < NN) {
                float4 v; float sc;
                if (k < 128) {
                    sc = 1.f / fmaxf(g_cnt[gr], 1.f);
                    v = ((const float4*)&g_agg[(size_t)gr * HD])[q];
                    if (ZERO_AGG)
                        ((float4*)&g_agg[(size_t)gr * HD])[q] =
                            make_float4(0.f, 0.f, 0.f, 0.f);
                } else {
                    sc = 1.f;
                    v = ((const float4*)&xin[(size_t)gr * HD])[q - 32];
                }
                v.x *= sc; v.y *= sc; v.z *= sc; v.w *= sc;
                split4(v, hv, lv);
            }
            uint32_t off = (uint32_t)(r * WP + k) * 2;
            *(uint2*)(smem + SMB_AHI + off) = hv;
            *(uint2*)(smem + SMB_ALO + off) = lv;
        }
        __syncthreads();

        // ---- mma: warp w -> rows m0, cols n0 (16 x 64 per warp) ----
        float acc[8][4];
#pragma unroll
        for (int j = 0; j < 8; j++)
#pragma unroll
            for (int c = 0; c < 4; c++) acc[j][c] = 0.f;

#pragma unroll 1
        for (int p = 0; p < 3; p++) {
            uint32_t Abase = sb + ((p == 2) ? SMB_ALO : SMB_AHI);
            uint32_t Wbase = sb + ((p == 1) ? SMB_WLO : SMB_WHI);
            uint32_t aaddr = Abase + (a_row * WP + a_koff) * 2;
            uint32_t baddr0 = Wbase + (b_row_base * WP + b_koff) * 2;
#pragma unroll
            for (int s = 0; s < 16; s++) {
                uint32_t k0b = (uint32_t)(s << 4) * 2;
                uint32_t a0, a1, a2, a3;
                ldsm_x4(a0, a1, a2, a3, aaddr + k0b);
#pragma unroll
                for (int jt = 0; jt < 4; jt++) {
                    uint32_t b0, b1, b2, b3;
                    ldsm_x4(b0, b1, b2, b3,
                            baddr0 + (uint32_t)(jt * 16 * WP) * 2 + k0b);
                    mma16816(acc[jt * 2], a0, a1, a2, a3, b0, b1);
                    mma16816(acc[jt * 2 + 1], a0, a1, a2, a3, b2, b3);
                }
            }
        }

        // ---- epilogue: bias (+relu), store fp32 ----
        int r_lo = row0 + m0 + gid;
        int r_hi = r_lo + 8;
#pragma unroll
        for (int j = 0; j < 8; j++) {
            int col = n0 + j * 8 + tq * 2;
            float b0 = sbias[col], b1 = sbias[col + 1];
            if (r_lo < NN) {
                float v0 = acc[j][0] + b0, v1 = acc[j][1] + b1;
                if (RELU) { v0 = fmaxf(v0, 0.f); v1 = fmaxf(v1, 0.f); }
                *(float2*)&outp[(size_t)r_lo * HD + col] = make_float2(v0, v1);
            }
            if (r_hi < NN) {
                float v2 = acc[j][2] + b0, v3 = acc[j][3] + b1;
                if (RELU) { v2 = fmaxf(v2, 0.f); v3 = fmaxf(v3, 0.f); }
                *(float2*)&outp[(size_t)r_hi * HD + col] = make_float2(v2, v3);
            }
        }
        __syncthreads();   // A smem reusable next iteration
    }
}

// ================= launch =================
extern "C" void kernel_launch(void* const* d_in, const int* in_sizes, int n_in,
                              void* d_out, int out_size) {
    const int* node_id = (const int*)d_in[0];
    const int* edge_index = (const int*)d_in[1];
    const float* emb = (const float*)d_in[2];
    const float* Wl1 = (const float*)d_in[3];
    const float* bl1 = (const float*)d_in[4];
    const float* Wr1 = (const float*)d_in[5];
    const float* Wl2 = (const float*)d_in[6];
    const float* bl2 = (const float*)d_in[7];
    const float* Wr2 = (const float*)d_in[8];
    const int* src = edge_index;
    const int* dst = edge_index + NE;
    float* outp = (float*)d_out;

    float *px, *ph1, *ph2;
    cudaGetSymbolAddress((void**)&px, g_x);
    cudaGetSymbolAddress((void**)&ph1, g_h1);
    cudaGetSymbolAddress((void**)&ph2, g_h2);

    cudaFuncSetAttribute(tc_layer_kernel<true, true>,
                         cudaFuncAttributeMaxDynamicSharedMemorySize, SMB_TOT);
    cudaFuncSetAttribute(tc_layer_kernel<false, false>,
                         cudaFuncAttributeMaxDynamicSharedMemorySize, SMB_TOT);

    const int TB = 256;
    int g_prep = (NN * 32 + TB - 1) / TB;
    int g_cnt_ = (NE + TB - 1) / TB;
    int g_scat = (NE * 32 + TB - 1) / TB;
    int g_edge = (NE * 8 + TB - 1) / TB;
    const int g_lay = 148;   // persistent: one CTA per SM

    prep_kernel<<<g_prep, TB>>>(node_id, emb);
    count_kernel<<<g_cnt_, TB>>>(dst);
    scatter_kernel<<<g_scat, TB>>>(px, src, dst);
    tc_layer_kernel<true, true><<<g_lay, TB, SMB_TOT>>>(Wl1, bl1, Wr1, px, ph1);
    scatter_kernel<<<g_scat, TB>>>(ph1, src, dst);
    tc_layer_kernel<false, false><<<g_lay, TB, SMB_TOT>>>(Wl2, bl2, Wr2, ph1, ph2);
    edge_dot_kernel<<<g_edge, TB>>>(src, dst, outp);
}

// round 6
// speedup vs baseline: 1.3051x; 1.1040x over previous
#include <cuda_runtime.h>
#include <cuda_bf16.h>
#include <cstdint>

#define NN 50000
#define NE 800000
#define HD 128
#define NTILES ((NN + 63) / 64)

// ---- scratch (device globals; no allocation allowed) ----
__device__ __align__(256) float g_x[NN * HD];
__device__ __align__(256) float g_agg[NN * HD];
__device__ __align__(256) float g_h1[NN * HD];
__device__ __align__(256) float g_h2[NN * HD];
__device__ __align__(256) float g_cnt[NN];

__device__ __forceinline__ uint32_t smem_to_u32(const void* smem_ptr) {
    uint32_t addr;
    asm("{ .reg .u64 tmp; cvta.to.shared.u64 tmp, %1; cvt.u32.u64 %0, tmp; }"
        : "=r"(addr) : "l"(smem_ptr));
    return addr;
}

__device__ __forceinline__ void red_add_v4(float* addr, float4 v) {
    asm volatile("red.global.add.v4.f32 [%0], {%1,%2,%3,%4};"
                 :: "l"(addr), "f"(v.x), "f"(v.y), "f"(v.z), "f"(v.w)
                 : "memory");
}
__device__ __forceinline__ void red_add_f(float* addr, float v) {
    asm volatile("red.global.add.f32 [%0], %1;" :: "l"(addr), "f"(v) : "memory");
}

// ================= graph-op kernels =================
__global__ void prep_kernel(const int* __restrict__ node_id,
                            const float* __restrict__ emb) {
    int t = blockIdx.x * blockDim.x + threadIdx.x;
    if (t >= NN * 32) return;
    int row = t >> 5, q = t & 31;
    int nid = node_id[row];
    float4 v = ((const float4*)emb)[(size_t)nid * 32 + q];
    ((float4*)g_x)[(size_t)row * 32 + q] = v;
    ((float4*)g_agg)[t] = make_float4(0.f, 0.f, 0.f, 0.f);
    if (q == 0) g_cnt[row] = 0.f;
}

// scatter (+optional count on lane 0): warp per edge
template <bool COUNT>
__global__ void scatter_kernel(const float* __restrict__ feat,
                               const int* __restrict__ src,
                               const int* __restrict__ dst) {
    int gt = blockIdx.x * blockDim.x + threadIdx.x;
    int e = gt >> 5;
    if (e >= NE) return;
    int lane = gt & 31;
    int s = src[e], d = dst[e];
    float4 v = ((const float4*)feat)[(size_t)s * 32 + lane];
    red_add_v4(&g_agg[(size_t)d * HD + lane * 4], v);
    if (COUNT && lane == 0) red_add_f(&g_cnt[d], 1.0f);
}

__global__ void edge_dot_kernel(const int* __restrict__ src,
                                const int* __restrict__ dst,
                                float* __restrict__ outp) {
    int gt = blockIdx.x * blockDim.x + threadIdx.x;
    int e = gt >> 3;
    if (e >= NE) return;
    int sub = gt & 7;
    int s = src[e], d = dst[e];
    const float4* hs = (const float4*)&g_h2[(size_t)s * HD];
    const float4* hd = (const float4*)&g_h2[(size_t)d * HD];
    float acc = 0.f;
#pragma unroll
    for (int t = 0; t < 4; t++) {
        float4 a = hs[sub + t * 8];
        float4 b = hd[sub + t * 8];
        acc += a.x * b.x + a.y * b.y + a.z * b.z + a.w * b.w;
    }
    acc += __shfl_xor_sync(0xffffffffu, acc, 1);
    acc += __shfl_xor_sync(0xffffffffu, acc, 2);
    acc += __shfl_xor_sync(0xffffffffu, acc, 4);
    if (sub == 0) outp[e] = acc;
}

// ================= persistent mma.sync split-bf16 SAGE layer =================
// out[m, 0:128] = concat(agg/max(cnt,1), x)[m, 0:256] @ Wcat^T + bl  (+relu)
// 3 passes: Ah*Wh + Ah*Wl + Al*Wh, fp32 accumulation.
// 512 threads (16 warps: 4 M-groups x 4 N-quarters), persistent grid=148.
#define TILE_M 64
#define WP 264
#define SMB_BIAS 0
#define SMB_WHI  512
#define SMB_WLO  (512 + 128 * WP * 2)
#define SMB_AHI  (512 + 2 * 128 * WP * 2)
#define SMB_ALO  (SMB_AHI + TILE_M * WP * 2)
#define SMB_TOT  (SMB_ALO + TILE_M * WP * 2)

__device__ __forceinline__ uint32_t pack_bf2(float lo, float hi) {
    uint32_t r;
    asm("cvt.rn.bf16x2.f32 %0, %1, %2;" : "=r"(r) : "f"(hi), "f"(lo));
    return r;
}
__device__ __forceinline__ void split4(float4 v, uint2& hv, uint2& lv) {
    hv.x = pack_bf2(v.x, v.y);
    hv.y = pack_bf2(v.z, v.w);
    float rx = v.x - __uint_as_float(hv.x << 16);
    float ry = v.y - __uint_as_float(hv.x & 0xffff0000u);
    float rz = v.z - __uint_as_float(hv.y << 16);
    float rw = v.w - __uint_as_float(hv.y & 0xffff0000u);
    lv.x = pack_bf2(rx, ry);
    lv.y = pack_bf2(rz, rw);
}

__device__ __forceinline__ void ldsm_x4(uint32_t& r0, uint32_t& r1,
                                        uint32_t& r2, uint32_t& r3, uint32_t a) {
    asm volatile("ldmatrix.sync.aligned.m8n8.x4.shared.b16 {%0,%1,%2,%3}, [%4];"
                 : "=r"(r0), "=r"(r1), "=r"(r2), "=r"(r3) : "r"(a));
}

__device__ __forceinline__ void mma16816(float* c, uint32_t a0, uint32_t a1,
                                         uint32_t a2, uint32_t a3,
                                         uint32_t b0, uint32_t b1) {
    asm volatile(
        "mma.sync.aligned.m16n8k16.row.col.f32.bf16.bf16.f32 "
        "{%0,%1,%2,%3}, {%4,%5,%6,%7}, {%8,%9}, {%0,%1,%2,%3};"
        : "+f"(c[0]), "+f"(c[1]), "+f"(c[2]), "+f"(c[3])
        : "r"(a0), "r"(a1), "r"(a2), "r"(a3), "r"(b0), "r"(b1));
}

template <bool RELU, bool ZERO_AGG>
__global__ __launch_bounds__(512, 1)
void tc_layer_kernel(const float* __restrict__ Wl, const float* __restrict__ bl,
                     const float* __restrict__ Wr,
                     const float* __restrict__ xin, float* __restrict__ outp) {
    extern __shared__ char smem[];
    uint32_t sb = smem_to_u32(smem);
    int tid = threadIdx.x;
    int lane = tid & 31;
    int wid = tid >> 5;

    if (tid < 128) ((float*)(smem + SMB_BIAS))[tid] = bl[tid];

    // ---- W (128 x 256) split into hi/lo smem: ONCE per CTA ----
#pragma unroll 4
    for (int idx = tid; idx < 128 * 64; idx += 512) {
        int n = idx >> 6, q = idx & 63, k = q << 2;
        float4 v = (k < 128) ? ((const float4*)Wl)[n * 32 + q]
                             : ((const float4*)Wr)[n * 32 + q - 32];
        uint2 hv, lv;
        split4(v, hv, lv);
        uint32_t off = (uint32_t)(n * WP + k) * 2;
        *(uint2*)(smem + SMB_WHI + off) = hv;
        *(uint2*)(smem + SMB_WLO + off) = lv;
    }
    __syncthreads();

    // warp tile: 16 rows x 32 cols
    int m0 = (wid >> 2) * 16;
    int n0 = (wid & 3) * 32;
    uint32_t a_row = (uint32_t)(m0 + (lane & 15));
    uint32_t a_koff = (uint32_t)((lane >> 4) << 3);
    uint32_t b_row_base = (uint32_t)(n0 + ((lane >> 4) << 3) + (lane & 7));
    uint32_t b_koff = (uint32_t)(((lane >> 3) & 1) << 3);
    const float* sbias = (const float*)(smem + SMB_BIAS);
    int gid = lane >> 2, tq = lane & 3;

    for (int t = blockIdx.x; t < NTILES; t += gridDim.x) {
        int row0 = t * TILE_M;

        // ---- A tile (64 x 256 = [agg/cnt | x]) load + split ----
#pragma unroll 4
        for (int idx = tid; idx < TILE_M * 64; idx += 512) {
            int r = idx >> 6, q = idx & 63, k = q << 2;
            int gr = row0 + r;
            uint2 hv = make_uint2(0u, 0u), lv = hv;
            if (gr < NN) {
                float4 v; float sc;
                if (k < 128) {
                    sc = 1.f / fmaxf(g_cnt[gr], 1.f);
                    v = ((const float4*)&g_agg[(size_t)gr * HD])[q];
                    if (ZERO_AGG)
                        ((float4*)&g_agg[(size_t)gr * HD])[q] =
                            make_float4(0.f, 0.f, 0.f, 0.f);
                } else {
                    sc = 1.f;
                    v = ((const float4*)&xin[(size_t)gr * HD])[q - 32];
                }
                v.x *= sc; v.y *= sc; v.z *= sc; v.w *= sc;
                split4(v, hv, lv);
            }
            uint32_t off = (uint32_t)(r * WP + k) * 2;
            *(uint2*)(smem + SMB_AHI + off) = hv;
            *(uint2*)(smem + SMB_ALO + off) = lv;
        }
        __syncthreads();

        // ---- mma with explicit k-step pipeline ----
        float acc[4][4];
#pragma unroll
        for (int j = 0; j < 4; j++)
#pragma unroll
            for (int c = 0; c < 4; c++) acc[j][c] = 0.f;

#pragma unroll 1
        for (int p = 0; p < 3; p++) {
            uint32_t Abase = sb + ((p == 2) ? SMB_ALO : SMB_AHI);
            uint32_t Wbase = sb + ((p == 1) ? SMB_WLO : SMB_WHI);
            uint32_t aaddr = Abase + (a_row * WP + a_koff) * 2;
            uint32_t baddr = Wbase + (b_row_base * WP + b_koff) * 2;

            uint32_t ca[4], cb0[4], cb1[4];
            ldsm_x4(ca[0], ca[1], ca[2], ca[3], aaddr);
            ldsm_x4(cb0[0], cb0[1], cb0[2], cb0[3], baddr);
            ldsm_x4(cb1[0], cb1[1], cb1[2], cb1[3],
                    baddr + (uint32_t)(16 * WP) * 2);
#pragma unroll
            for (int s = 0; s < 16; s++) {
                uint32_t na[4], nb0[4], nb1[4];
                if (s < 15) {
                    uint32_t k0b = (uint32_t)((s + 1) << 4) * 2;
                    ldsm_x4(na[0], na[1], na[2], na[3], aaddr + k0b);
                    ldsm_x4(nb0[0], nb0[1], nb0[2], nb0[3], baddr + k0b);
                    ldsm_x4(nb1[0], nb1[1], nb1[2], nb1[3],
                            baddr + (uint32_t)(16 * WP) * 2 + k0b);
                }
                mma16816(acc[0], ca[0], ca[1], ca[2], ca[3], cb0[0], cb0[1]);
                mma16816(acc[1], ca[0], ca[1], ca[2], ca[3], cb0[2], cb0[3]);
                mma16816(acc[2], ca[0], ca[1], ca[2], ca[3], cb1[0], cb1[1]);
                mma16816(acc[3], ca[0], ca[1], ca[2], ca[3], cb1[2], cb1[3]);
                if (s < 15) {
#pragma unroll
                    for (int r = 0; r < 4; r++) {
                        ca[r] = na[r]; cb0[r] = nb0[r]; cb1[r] = nb1[r];
                    }
                }
            }
        }

        // ---- epilogue: bias (+relu), store fp32 ----
        int r_lo = row0 + m0 + gid;
        int r_hi = r_lo + 8;
#pragma unroll
        for (int j = 0; j < 4; j++) {
            int col = n0 + j * 8 + tq * 2;
            float b0 = sbias[col], b1 = sbias[col + 1];
            if (r_lo < NN) {
                float v0 = acc[j][0] + b0, v1 = acc[j][1] + b1;
                if (RELU) { v0 = fmaxf(v0, 0.f); v1 = fmaxf(v1, 0.f); }
                *(float2*)&outp[(size_t)r_lo * HD + col] = make_float2(v0, v1);
            }
            if (r_hi < NN) {
                float v2 = acc[j][2] + b0, v3 = acc[j][3] + b1;
                if (RELU) { v2 = fmaxf(v2, 0.f); v3 = fmaxf(v3, 0.f); }
                *(float2*)&outp[(size_t)r_hi * HD + col] = make_float2(v2, v3);
            }
        }
        __syncthreads();
    }
}

// ================= launch =================
extern "C" void kernel_launch(void* const* d_in, const int* in_sizes, int n_in,
                              void* d_out, int out_size) {
    const int* node_id = (const int*)d_in[0];
    const int* edge_index = (const int*)d_in[1];
    const float* emb = (const float*)d_in[2];
    const float* Wl1 = (const float*)d_in[3];
    const float* bl1 = (const float*)d_in[4];
    const float* Wr1 = (const float*)d_in[5];
    const float* Wl2 = (const float*)d_in[6];
    const float* bl2 = (const float*)d_in[7];
    const float* Wr2 = (const float*)d_in[8];
    const int* src = edge_index;
    const int* dst = edge_index + NE;
    float* outp = (float*)d_out;

    float *px, *ph1, *ph2;
    cudaGetSymbolAddress((void**)&px, g_x);
    cudaGetSymbolAddress((void**)&ph1, g_h1);
    cudaGetSymbolAddress((void**)&ph2, g_h2);

    cudaFuncSetAttribute(tc_layer_kernel<true, true>,
                         cudaFuncAttributeMaxDynamicSharedMemorySize, SMB_TOT);
    cudaFuncSetAttribute(tc_layer_kernel<false, false>,
                         cudaFuncAttributeMaxDynamicSharedMemorySize, SMB_TOT);

    const int TB = 256;
    int g_prep = (NN * 32 + TB - 1) / TB;
    int g_scat = (NE * 32 + TB - 1) / TB;
    int g_edge = (NE * 8 + TB - 1) / TB;
    const int g_lay = 148;

    prep_kernel<<<g_prep, TB>>>(node_id, emb);
    scatter_kernel<true><<<g_scat, TB>>>(px, src, dst);
    tc_layer_kernel<true, true><<<g_lay, 512, SMB_TOT>>>(Wl1, bl1, Wr1, px, ph1);
    scatter_kernel<false><<<g_scat, TB>>>(ph1, src, dst);
    tc_layer_kernel<false, false><<<g_lay, 512, SMB_TOT>>>(Wl2, bl2, Wr2, ph1, ph2);
    edge_dot_kernel<<<g_edge, TB>>>(src, dst, outp);
}

// round 10
// speedup vs baseline: 2.1533x; 1.6499x over previous
#include <cuda_runtime.h>
#include <cuda_bf16.h>
#include <cstdint>

#define NN 50000
#define NE 800000
#define HD 128
#define NTILES ((NN + 63) / 64)
#define SCAN_BS 512
#define NBLK ((NN + SCAN_BS - 1) / SCAN_BS)

// ---- scratch (device globals; no allocation allowed) ----
__device__ __align__(256) float g_x[NN * HD];
__device__ __align__(256) float g_agg[NN * HD];
__device__ __align__(256) float g_h1[NN * HD];
__device__ __align__(256) float g_h2[NN * HD];
__device__ int g_deg[NN];
__device__ int g_off[NN + 1];
__device__ int g_cur[NN];
__device__ int g_bsum[NBLK];
__device__ int g_boff[NBLK];
__device__ int g_ssrc[NE];   // src ids grouped by dst

__device__ __forceinline__ uint32_t smem_to_u32(const void* smem_ptr) {
    uint32_t addr;
    asm("{ .reg .u64 tmp; cvta.to.shared.u64 tmp, %1; cvt.u32.u64 %0, tmp; }"
        : "=r"(addr) : "l"(smem_ptr));
    return addr;
}

// ================= prep: gather x = emb[node_id]; zero deg =================
__global__ void prep_kernel(const int* __restrict__ node_id,
                            const float* __restrict__ emb) {
    int t = blockIdx.x * blockDim.x + threadIdx.x;
    if (t >= NN * 32) return;
    int row = t >> 5, q = t & 31;
    int nid = node_id[row];
    float4 v = ((const float4*)emb)[(size_t)nid * 32 + q];
    ((float4*)g_x)[(size_t)row * 32 + q] = v;
    if (q == 0) g_deg[row] = 0;
}

// ================= counting sort of edges by dst =================
__global__ void hist_kernel(const int* __restrict__ dst) {
    int e = blockIdx.x * blockDim.x + threadIdx.x;
    if (e < NE) atomicAdd(&g_deg[dst[e]], 1);
}

__global__ void scan1_kernel() {
    __shared__ int sh[SCAN_BS];
    int tid = threadIdx.x;
    int i = blockIdx.x * SCAN_BS + tid;
    int v = (i < NN) ? g_deg[i] : 0;
    sh[tid] = v;
    __syncthreads();
#pragma unroll
    for (int d = 1; d < SCAN_BS; d <<= 1) {
        int t = (tid >= d) ? sh[tid - d] : 0;
        __syncthreads();
        sh[tid] += t;
        __syncthreads();
    }
    if (i < NN) g_off[i] = sh[tid] - v;      // exclusive within block
    if (tid == SCAN_BS - 1) g_bsum[blockIdx.x] = sh[tid];
}

__global__ void scan2_kernel() {
    if (threadIdx.x == 0) {
        int run = 0;
        for (int i = 0; i < NBLK; i++) {
            g_boff[i] = run;
            run += g_bsum[i];
        }
    }
}

__global__ void scan3_kernel() {
    int i = blockIdx.x * blockDim.x + threadIdx.x;
    if (i < NN) {
        int o = g_off[i] + g_boff[i / SCAN_BS];
        g_off[i] = o;
        g_cur[i] = o;
    }
    if (i == 0) g_off[NN] = NE;
}

__global__ void fill_kernel(const int* __restrict__ src,
                            const int* __restrict__ dst) {
    int e = blockIdx.x * blockDim.x + threadIdx.x;
    if (e >= NE) return;
    int d = dst[e];
    int pos = atomicAdd(&g_cur[d], 1);
    g_ssrc[pos] = src[e];
}

// ================= aggregation: warp per node, no atomics =================
// g_agg[node] = mean over grouped edges of feat[src]   (0 if deg==0)
__global__ __launch_bounds__(256)
void agg_kernel(const float* __restrict__ feat) {
    int node = blockIdx.x * 8 + (threadIdx.x >> 5);
    if (node >= NN) return;
    int lane = threadIdx.x & 31;
    int beg = g_off[node], end = g_off[node + 1];
    float4 acc = make_float4(0.f, 0.f, 0.f, 0.f);
    int j = beg;
    for (; j + 4 <= end; j += 4) {
        int s0 = g_ssrc[j], s1 = g_ssrc[j + 1];
        int s2 = g_ssrc[j + 2], s3 = g_ssrc[j + 3];
        float4 v0 = ((const float4*)feat)[(size_t)s0 * 32 + lane];
        float4 v1 = ((const float4*)feat)[(size_t)s1 * 32 + lane];
        float4 v2 = ((const float4*)feat)[(size_t)s2 * 32 + lane];
        float4 v3 = ((const float4*)feat)[(size_t)s3 * 32 + lane];
        acc.x += v0.x + v1.x + v2.x + v3.x;
        acc.y += v0.y + v1.y + v2.y + v3.y;
        acc.z += v0.z + v1.z + v2.z + v3.z;
        acc.w += v0.w + v1.w + v2.w + v3.w;
    }
    for (; j < end; j++) {
        int s = g_ssrc[j];
        float4 v = ((const float4*)feat)[(size_t)s * 32 + lane];
        acc.x += v.x; acc.y += v.y; acc.z += v.z; acc.w += v.w;
    }
    float inv = (end > beg) ? 1.f / (float)(end - beg) : 0.f;
    acc.x *= inv; acc.y *= inv; acc.z *= inv; acc.w *= inv;
    ((float4*)g_agg)[(size_t)node * 32 + lane] = acc;
}

// ================= edge classifier =================
__global__ void edge_dot_kernel(const int* __restrict__ src,
                                const int* __restrict__ dst,
                                float* __restrict__ outp) {
    int gt = blockIdx.x * blockDim.x + threadIdx.x;
    int e = gt >> 3;
    if (e >= NE) return;
    int sub = gt & 7;
    int s = src[e], d = dst[e];
    const float4* hs = (const float4*)&g_h2[(size_t)s * HD];
    const float4* hd = (const float4*)&g_h2[(size_t)d * HD];
    float acc = 0.f;
#pragma unroll
    for (int t = 0; t < 4; t++) {
        float4 a = hs[sub + t * 8];
        float4 b = hd[sub + t * 8];
        acc += a.x * b.x + a.y * b.y + a.z * b.z + a.w * b.w;
    }
    acc += __shfl_xor_sync(0xffffffffu, acc, 1);
    acc += __shfl_xor_sync(0xffffffffu, acc, 2);
    acc += __shfl_xor_sync(0xffffffffu, acc, 4);
    if (sub == 0) outp[e] = acc;
}

// ================= persistent mma.sync split-bf16 SAGE layer =================
// out[m, 0:128] = concat(agg, x)[m, 0:256] @ Wcat^T + bl  (+relu)
// agg already contains the mean. 3 passes: Ah*Wh + Ah*Wl + Al*Wh.
#define TILE_M 64
#define WP 264
#define SMB_BIAS 0
#define SMB_WHI  512
#define SMB_WLO  (512 + 128 * WP * 2)
#define SMB_AHI  (512 + 2 * 128 * WP * 2)
#define SMB_ALO  (SMB_AHI + TILE_M * WP * 2)
#define SMB_TOT  (SMB_ALO + TILE_M * WP * 2)

__device__ __forceinline__ uint32_t pack_bf2(float lo, float hi) {
    uint32_t r;
    asm("cvt.rn.bf16x2.f32 %0, %1, %2;" : "=r"(r) : "f"(hi), "f"(lo));
    return r;
}
__device__ __forceinline__ void split4(float4 v, uint2& hv, uint2& lv) {
    hv.x = pack_bf2(v.x, v.y);
    hv.y = pack_bf2(v.z, v.w);
    float rx = v.x - __uint_as_float(hv.x << 16);
    float ry = v.y - __uint_as_float(hv.x & 0xffff0000u);
    float rz = v.z - __uint_as_float(hv.y << 16);
    float rw = v.w - __uint_as_float(hv.y & 0xffff0000u);
    lv.x = pack_bf2(rx, ry);
    lv.y = pack_bf2(rz, rw);
}

__device__ __forceinline__ void ldsm_x4(uint32_t& r0, uint32_t& r1,
                                        uint32_t& r2, uint32_t& r3, uint32_t a) {
    asm volatile("ldmatrix.sync.aligned.m8n8.x4.shared.b16 {%0,%1,%2,%3}, [%4];"
                 : "=r"(r0), "=r"(r1), "=r"(r2), "=r"(r3) : "r"(a));
}

__device__ __forceinline__ void mma16816(float* c, uint32_t a0, uint32_t a1,
                                         uint32_t a2, uint32_t a3,
                                         uint32_t b0, uint32_t b1) {
    asm volatile(
        "mma.sync.aligned.m16n8k16.row.col.f32.bf16.bf16.f32 "
        "{%0,%1,%2,%3}, {%4,%5,%6,%7}, {%8,%9}, {%0,%1,%2,%3};"
        : "+f"(c[0]), "+f"(c[1]), "+f"(c[2]), "+f"(c[3])
        : "r"(a0), "r"(a1), "r"(a2), "r"(a3), "r"(b0), "r"(b1));
}

template <bool RELU>
__global__ __launch_bounds__(512, 1)
void tc_layer_kernel(const float* __restrict__ Wl, const float* __restrict__ bl,
                     const float* __restrict__ Wr,
                     const float* __restrict__ xin, float* __restrict__ outp) {
    extern __shared__ char smem[];
    uint32_t sb = smem_to_u32(smem);
    int tid = threadIdx.x;
    int lane = tid & 31;
    int wid = tid >> 5;

    if (tid < 128) ((float*)(smem + SMB_BIAS))[tid] = bl[tid];

    // ---- W (128 x 256) split into hi/lo smem: ONCE per CTA ----
#pragma unroll 4
    for (int idx = tid; idx < 128 * 64; idx += 512) {
        int n = idx >> 6, q = idx & 63, k = q << 2;
        float4 v = (k < 128) ? ((const float4*)Wl)[n * 32 + q]
                             : ((const float4*)Wr)[n * 32 + q - 32];
        uint2 hv, lv;
        split4(v, hv, lv);
        uint32_t off = (uint32_t)(n * WP + k) * 2;
        *(uint2*)(smem + SMB_WHI + off) = hv;
        *(uint2*)(smem + SMB_WLO + off) = lv;
    }
    __syncthreads();

    // warp tile: 16 rows x 32 cols
    int m0 = (wid >> 2) * 16;
    int n0 = (wid & 3) * 32;
    uint32_t a_row = (uint32_t)(m0 + (lane & 15));
    uint32_t a_koff = (uint32_t)((lane >> 4) << 3);
    uint32_t b_row_base = (uint32_t)(n0 + ((lane >> 4) << 3) + (lane & 7));
    uint32_t b_koff = (uint32_t)(((lane >> 3) & 1) << 3);
    const float* sbias = (const float*)(smem + SMB_BIAS);
    int gid = lane >> 2, tq = lane & 3;

    for (int t = blockIdx.x; t < NTILES; t += gridDim.x) {
        int row0 = t * TILE_M;

        // ---- A tile (64 x 256 = [agg | x]) load + split ----
#pragma unroll 4
        for (int idx = tid; idx < TILE_M * 64; idx += 512) {
            int r = idx >> 6, q = idx & 63, k = q << 2;
            int gr = row0 + r;
            uint2 hv = make_uint2(0u, 0u), lv = hv;
            if (gr < NN) {
                float4 v = (k < 128)
                    ? ((const float4*)&g_agg[(size_t)gr * HD])[q]
                    : ((const float4*)&xin[(size_t)gr * HD])[q - 32];
                split4(v, hv, lv);
            }
            uint32_t off = (uint32_t)(r * WP + k) * 2;
            *(uint2*)(smem + SMB_AHI + off) = hv;
            *(uint2*)(smem + SMB_ALO + off) = lv;
        }
        __syncthreads();

        // ---- mma with explicit k-step pipeline ----
        float acc[4][4];
#pragma unroll
        for (int j = 0; j < 4; j++)
#pragma unroll
            for (int c = 0; c < 4; c++) acc[j][c] = 0.f;

#pragma unroll 1
        for (int p = 0; p < 3; p++) {
            uint32_t Abase = sb + ((p == 2) ? SMB_ALO : SMB_AHI);
            uint32_t Wbase = sb + ((p == 1) ? SMB_WLO : SMB_WHI);
            uint32_t aaddr = Abase + (a_row * WP + a_koff) * 2;
            uint32_t baddr = Wbase + (b_row_base * WP + b_koff) * 2;

            uint32_t ca[4], cb0[4], cb1[4];
            ldsm_x4(ca[0], ca[1], ca[2], ca[3], aaddr);
            ldsm_x4(cb0[0], cb0[1], cb0[2], cb0[3], baddr);
            ldsm_x4(cb1[0], cb1[1], cb1[2], cb1[3],
                    baddr + (uint32_t)(16 * WP) * 2);
#pragma unroll
            for (int s = 0; s < 16; s++) {
                uint32_t na[4], nb0[4], nb1[4];
                if (s < 15) {
                    uint32_t k0b = (uint32_t)((s + 1) << 4) * 2;
                    ldsm_x4(na[0], na[1], na[2], na[3], aaddr + k0b);
                    ldsm_x4(nb0[0], nb0[1], nb0[2], nb0[3], baddr + k0b);
                    ldsm_x4(nb1[0], nb1[1], nb1[2], nb1[3],
                            baddr + (uint32_t)(16 * WP) * 2 + k0b);
                }
                mma16816(acc[0], ca[0], ca[1], ca[2], ca[3], cb0[0], cb0[1]);
                mma16816(acc[1], ca[0], ca[1], ca[2], ca[3], cb0[2], cb0[3]);
                mma16816(acc[2], ca[0], ca[1], ca[2], ca[3], cb1[0], cb1[1]);
                mma16816(acc[3], ca[0], ca[1], ca[2], ca[3], cb1[2], cb1[3]);
                if (s < 15) {
#pragma unroll
                    for (int r = 0; r < 4; r++) {
                        ca[r] = na[r]; cb0[r] = nb0[r]; cb1[r] = nb1[r];
                    }
                }
            }
        }

        // ---- epilogue: bias (+relu), store fp32 ----
        int r_lo = row0 + m0 + gid;
        int r_hi = r_lo + 8;
#pragma unroll
        for (int j = 0; j < 4; j++) {
            int col = n0 + j * 8 + tq * 2;
            float b0 = sbias[col], b1 = sbias[col + 1];
            if (r_lo < NN) {
                float v0 = acc[j][0] + b0, v1 = acc[j][1] + b1;
                if (RELU) { v0 = fmaxf(v0, 0.f); v1 = fmaxf(v1, 0.f); }
                *(float2*)&outp[(size_t)r_lo * HD + col] = make_float2(v0, v1);
            }
            if (r_hi < NN) {
                float v2 = acc[j][2] + b0, v3 = acc[j][3] + b1;
                if (RELU) { v2 = fmaxf(v2, 0.f); v3 = fmaxf(v3, 0.f); }
                *(float2*)&outp[(size_t)r_hi * HD + col] = make_float2(v2, v3);
            }
        }
        __syncthreads();
    }
}

// ================= launch =================
extern "C" void kernel_launch(void* const* d_in, const int* in_sizes, int n_in,
                              void* d_out, int out_size) {
    const int* node_id = (const int*)d_in[0];
    const int* edge_index = (const int*)d_in[1];
    const float* emb = (const float*)d_in[2];
    const float* Wl1 = (const float*)d_in[3];
    const float* bl1 = (const float*)d_in[4];
    const float* Wr1 = (const float*)d_in[5];
    const float* Wl2 = (const float*)d_in[6];
    const float* bl2 = (const float*)d_in[7];
    const float* Wr2 = (const float*)d_in[8];
    const int* src = edge_index;
    const int* dst = edge_index + NE;
    float* outp = (float*)d_out;

    float *px, *ph1, *ph2;
    cudaGetSymbolAddress((void**)&px, g_x);
    cudaGetSymbolAddress((void**)&ph1, g_h1);
    cudaGetSymbolAddress((void**)&ph2, g_h2);

    cudaFuncSetAttribute(tc_layer_kernel<true>,
                         cudaFuncAttributeMaxDynamicSharedMemorySize, SMB_TOT);
    cudaFuncSetAttribute(tc_layer_kernel<false>,
                         cudaFuncAttributeMaxDynamicSharedMemorySize, SMB_TOT);

    const int TB = 256;
    int g_prep = (NN * 32 + TB - 1) / TB;
    int g_edge1 = (NE + TB - 1) / TB;
    int g_nodes = (NN + TB - 1) / TB;
    int g_agg  = (NN + 7) / 8;
    int g_edge8 = (NE * 8 + TB - 1) / TB;
    const int g_lay = 148;

    prep_kernel<<<g_prep, TB>>>(node_id, emb);
    hist_kernel<<<g_edge1, TB>>>(dst);
    scan1_kernel<<<NBLK, SCAN_BS>>>();
    scan2_kernel<<<1, 32>>>();
    scan3_kernel<<<g_nodes, TB>>>();
    fill_kernel<<<g_edge1, TB>>>(src, dst);
    agg_kernel<<<g_agg, TB>>>(px);
    tc_layer_kernel<true><<<g_lay, 512, SMB_TOT>>>(Wl1, bl1, Wr1, px, ph1);
    agg_kernel<<<g_agg, TB>>>(ph1);
    tc_layer_kernel<false><<<g_lay, 512, SMB_TOT>>>(Wl2, bl2, Wr2, ph1, ph2);
    edge_dot_kernel<<<g_edge8, TB>>>(src, dst, outp);
}